// round 17
// baseline (speedup 1.0000x reference)
#include <cuda_runtime.h>
#include <cuda_fp16.h>
#include <math.h>
#include <stdint.h>

#define NN 50000
#define EE 800000
#define DD 128
#define OUTC 64
#define NBLK ((NN + 1023) / 1024)   // 49 scan blocks

typedef unsigned long long u64;

// ---------------- scratch (device globals; no allocation allowed) ----------
__device__ int   g_ei_is64;
__device__ int   g_m_is32;
__device__ int   g_deg[NN];          // zero-init at load; re-zeroed each replay
__device__ float g_dinv[NN];
__device__ int   g_off[NN + 1];      // [i+1] = block-LOCAL inclusive; [0] stays 0
__device__ int   g_bsum[64];         // raw per-block sums from scanA
__device__ int   g_rank[EE];         // per-edge rank within its column
__device__ int   g_src[EE];
__device__ __half g_xt[NN * DD];     // x_tilde, fp16, pre-scaled by dinv[row]
__device__ __half g_x0[NN * DD];     // hrn(dinv*x) where mask=1, NaN where mask=0
__device__ __half g_agg[NN * DD];    // aggregated messages (fp16)
__device__ __half g_h[NN * DD];      // layer-3 activations (fp16)

// ---------------- f32x2 packed math ----------------------------------------
__device__ __forceinline__ u64 pack2(float s) {
    u64 d;
    asm("mov.b64 %0, {%1, %1};" : "=l"(d) : "f"(s));
    return d;
}
__device__ __forceinline__ void fma2(u64& acc, u64 a, u64 b) {
    asm("fma.rn.f32x2 %0, %1, %2, %0;" : "+l"(acc) : "l"(a), "l"(b));
}
__device__ __forceinline__ float2 unpack2(u64 v) {
    float lo, hi;
    asm("mov.b64 {%0, %1}, %2;" : "=f"(lo), "=f"(hi) : "l"(v));
    return make_float2(lo, hi);
}

// exclusive block-prefix of g_bsum into smem (call with >=64 threads, then sync)
__device__ __forceinline__ void load_bsum_prefix(int* sb, int tid) {
    if (tid < NBLK) sb[tid] = g_bsum[tid];
    __syncthreads();
    if (tid == 0) {
        int acc = 0;
#pragma unroll
        for (int q = 0; q < NBLK; q++) { int t = sb[q]; sb[q] = acc; acc += t; }
    }
    __syncthreads();
}
// global exclusive offset of column/node c (g_off holds block-local inclusive)
__device__ __forceinline__ int col_start(const int* sb, int c) {
    return (c > 0) ? (g_off[c] + sb[(c - 1) >> 10]) : 0;
}

// ---------------- count + dtype detection + deg-rezero handled at tail ------
__global__ void k_count(const int* __restrict__ ei, const unsigned int* __restrict__ Mw) {
    __shared__ int s_or;
    if (threadIdx.x == 0) s_or = 0;
    __syncthreads();
    if (threadIdx.x < 256 && ei[2 * threadIdx.x + 1] != 0) atomicOr(&s_or, 1);
    __syncthreads();
    int is64 = (s_or == 0);
    if (blockIdx.x == 0) {
        __shared__ int s_gt;
        if (threadIdx.x == 0) s_gt = 0;
        __syncthreads();
        if (threadIdx.x < 256 && Mw[threadIdx.x] > 1u) atomicOr(&s_gt, 1);
        __syncthreads();
        if (threadIdx.x == 0) { g_ei_is64 = is64; g_m_is32 = (s_gt == 0); }
    }
    int e = blockIdx.x * blockDim.x + threadIdx.x;
    if (e >= EE) return;
    int c = is64 ? ei[2 * (EE + e)] : ei[EE + e];
    g_rank[e] = atomicAdd(&g_deg[c], 1);
}

__global__ void k_scanA() {
    __shared__ int wsum[32];
    int tid = threadIdx.x, lane = tid & 31, wid = tid >> 5;
    int i = blockIdx.x * 1024 + tid;
    int v = (i < NN) ? g_deg[i] : 0;
    if (i < NN) g_dinv[i] = (v > 0) ? rsqrtf((float)v) : 0.0f;
    int x = v;
#pragma unroll
    for (int o = 1; o < 32; o <<= 1) {
        int t = __shfl_up_sync(0xffffffffu, x, o);
        if (lane >= o) x += t;
    }
    if (lane == 31) wsum[wid] = x;
    __syncthreads();
    if (wid == 0) {
        int s = wsum[lane];
#pragma unroll
        for (int o = 1; o < 32; o <<= 1) {
            int t = __shfl_up_sync(0xffffffffu, s, o);
            if (lane >= o) s += t;
        }
        wsum[lane] = s;
    }
    __syncthreads();
    int woff = (wid > 0) ? wsum[wid - 1] : 0;
    if (i < NN) g_off[i + 1] = woff + x;              // block-LOCAL inclusive
    if (tid == 1023) g_bsum[blockIdx.x] = woff + x;   // raw block sum
}

// ---------------- merged: x_tilde/x0 init + edge bucketing + deg rezero ------
// xt part: one (N*D)/4 element per thread (6250 blocks x 256).
// bucket part: edges grid-strided over the same grid; overlaps DRAM-bound xt
// with L2-bound scatter. Offsets derived locally from raw g_off + bsum prefix.
__global__ void k_xt_bucket(const float* __restrict__ x, const void* __restrict__ M,
                            const int* __restrict__ ei) {
    __shared__ int sb[NBLK];
    int tid = threadIdx.x;
    int gid = blockIdx.x * blockDim.x + tid;
    load_bsum_prefix(sb, tid);

    // ---- xt/x0 init ----
    if (gid < NN * DD / 4) {
        int i = gid;
        uchar4 mv;
        if (g_m_is32) {
            int4 w = ((const int4*)M)[i];
            mv = make_uchar4((unsigned char)w.x, (unsigned char)w.y,
                             (unsigned char)w.z, (unsigned char)w.w);
        } else {
            mv = ((const uchar4*)M)[i];
        }
        float dv = g_dinv[i >> 5];
        float4 xv = ((const float4*)x)[i];
        float s0 = dv * xv.x, s1 = dv * xv.y, s2 = dv * xv.z, s3 = dv * xv.w;
        __half2 xt01 = __floats2half2_rn(mv.x ? s0 : 0.0f, mv.y ? s1 : 0.0f);
        __half2 xt23 = __floats2half2_rn(mv.z ? s2 : 0.0f, mv.w ? s3 : 0.0f);
        const float QNAN = __int_as_float(0x7fc00000);
        __half2 x001 = __floats2half2_rn(mv.x ? s0 : QNAN, mv.y ? s1 : QNAN);
        __half2 x023 = __floats2half2_rn(mv.z ? s2 : QNAN, mv.w ? s3 : QNAN);
        uint2 pxt, px0;
        pxt.x = *(unsigned int*)&xt01; pxt.y = *(unsigned int*)&xt23;
        px0.x = *(unsigned int*)&x001; px0.y = *(unsigned int*)&x023;
        ((uint2*)g_xt)[i] = pxt;
        ((uint2*)g_x0)[i] = px0;
    }

    // ---- bucket (grid-stride over edges) + deg rezero for next replay ----
    int nthreads = gridDim.x * blockDim.x;
    int is64 = g_ei_is64;
    for (int e = gid; e < EE; e += nthreads) {
        if (e < NN) g_deg[e] = 0;
        int r, c;
        if (is64) { r = ei[2 * e]; c = ei[2 * (EE + e)]; }
        else      { r = ei[e];     c = ei[EE + e]; }
        g_src[col_start(sb, c) + g_rank[e]] = r;
    }
}

// ---------------- SpMM: one warp per destination node (fp16 in/out) ----------
__global__ void k_spmm() {
    __shared__ int sb[NBLK];
    int tid = threadIdx.x;
    load_bsum_prefix(sb, tid);
    int warp = (blockIdx.x * blockDim.x + tid) >> 5;
    if (warp >= NN) return;
    int lane = tid & 31;
    int s = col_start(sb, warp);
    int t = g_off[warp + 1] + sb[warp >> 10];        // start(warp+1)
    const uint2* xt2 = (const uint2*)g_xt;   // 8B = 4 halfs per lane
    float4 acc = make_float4(0.f, 0.f, 0.f, 0.f);
    int i = s;
    for (; i + 8 <= t; i += 8) {
        uint2 rv[8];
#pragma unroll
        for (int u = 0; u < 8; u++) rv[u] = xt2[g_src[i + u] * 32 + lane];
#pragma unroll
        for (int u = 0; u < 8; u++) {
            float2 f01 = __half22float2(*(__half2*)&rv[u].x);
            float2 f23 = __half22float2(*(__half2*)&rv[u].y);
            acc.x += f01.x; acc.y += f01.y; acc.z += f23.x; acc.w += f23.y;
        }
    }
    for (; i + 4 <= t; i += 4) {
        uint2 rv[4];
#pragma unroll
        for (int u = 0; u < 4; u++) rv[u] = xt2[g_src[i + u] * 32 + lane];
#pragma unroll
        for (int u = 0; u < 4; u++) {
            float2 f01 = __half22float2(*(__half2*)&rv[u].x);
            float2 f23 = __half22float2(*(__half2*)&rv[u].y);
            acc.x += f01.x; acc.y += f01.y; acc.z += f23.x; acc.w += f23.y;
        }
    }
    for (; i < t; i++) {
        uint2 rv = xt2[g_src[i] * 32 + lane];
        float2 f01 = __half22float2(*(__half2*)&rv.x);
        float2 f23 = __half22float2(*(__half2*)&rv.y);
        acc.x += f01.x; acc.y += f01.y; acc.z += f23.x; acc.w += f23.y;
    }
    float dv = g_dinv[warp];
    __half2 o01 = __floats2half2_rn(dv * acc.x, dv * acc.y);
    __half2 o23 = __floats2half2_rn(dv * acc.z, dv * acc.w);
    uint2 p;
    p.x = *(unsigned int*)&o01;
    p.y = *(unsigned int*)&o23;
    ((uint2*)g_agg)[warp * 32 + lane] = p;
}

// ---------------- GEMM, 64-row tiles, 128 threads ----------------------------
// D[64 x NOUT] = A[64 x 128] @ W[NOUT x 128]^T. A fp16 (g_agg / g_h).
template <int NOUT, bool FINAL>
__global__ void __launch_bounds__(128)
k_gemm(const float* __restrict__ W, const float* __restrict__ b,
       const float* __restrict__ bias,
       float* __restrict__ out, int write_xt) {
    constexpr int NPAIR = NOUT / 32;
    __shared__ float sA[64 * 33];        // [r][kk] chunk
    __shared__ float sW[32 * 130];       // [kk][j] chunk, 8B-aligned pairs
    __shared__ float sB[128];
    int tid = threadIdx.x;
    int row0 = blockIdx.x * 64;
    int tr = tid >> 4, tc = tid & 15;    // tr: 0..7

    if (tid < NOUT) sB[tid] = FINAL ? b[tid] : (b[tid] + bias[tid]);

    u64 acc[8][NPAIR];
#pragma unroll
    for (int ii = 0; ii < 8; ii++)
#pragma unroll
        for (int jj = 0; jj < NPAIR; jj++) acc[ii][jj] = 0ull;

    const float4* W4 = (const float4*)W;
    const uint2* A2 = (const uint2*)(FINAL ? g_h : g_agg);

    for (int kc = 0; kc < 4; kc++) {
        for (int t = tid; t < 64 * 8; t += 128) {
            int r = t >> 3, q = t & 7;
            uint2 v = (row0 + r < NN) ? A2[(size_t)(row0 + r) * 32 + kc * 8 + q]
                                      : make_uint2(0u, 0u);
            float2 f01 = __half22float2(*(__half2*)&v.x);
            float2 f23 = __half22float2(*(__half2*)&v.y);
            float* dst = &sA[r * 33 + q * 4];
            dst[0] = f01.x; dst[1] = f01.y; dst[2] = f23.x; dst[3] = f23.y;
        }
        for (int t = tid; t < NOUT * 8; t += 128) {
            int j = t >> 3, q = t & 7;
            float4 v = W4[(size_t)j * 32 + kc * 8 + q];
            int kk = q * 4;
            sW[(kk + 0) * 130 + j] = v.x;
            sW[(kk + 1) * 130 + j] = v.y;
            sW[(kk + 2) * 130 + j] = v.z;
            sW[(kk + 3) * 130 + j] = v.w;
        }
        __syncthreads();
#pragma unroll
        for (int kk = 0; kk < 32; kk++) {
            u64 a2[8], w2[NPAIR];
#pragma unroll
            for (int ii = 0; ii < 8; ii++)
                a2[ii] = pack2(sA[(tr + 8 * ii) * 33 + kk]);
#pragma unroll
            for (int jj = 0; jj < NPAIR; jj++)
                w2[jj] = *(const u64*)&sW[kk * 130 + 2 * tc + 32 * jj];
#pragma unroll
            for (int ii = 0; ii < 8; ii++)
#pragma unroll
                for (int jj = 0; jj < NPAIR; jj++)
                    fma2(acc[ii][jj], a2[ii], w2[jj]);
        }
        __syncthreads();
    }

#pragma unroll
    for (int ii = 0; ii < 8; ii++) {
        int r = row0 + tr + 8 * ii;
        if (r >= NN) continue;
        float dv = (!FINAL) ? g_dinv[r] : 0.f;
#pragma unroll
        for (int jj = 0; jj < NPAIR; jj++) {
            int j0 = 2 * tc + 32 * jj;
            float2 v = unpack2(acc[ii][jj]);
            if (FINAL) {
                v.x += sB[j0];
                v.y += sB[j0 + 1];
                *(float2*)&out[(size_t)r * OUTC + j0] = v;
            } else {
                v.x = fmaxf(v.x + sB[j0], 0.f);
                v.y = fmaxf(v.y + sB[j0 + 1], 0.f);
                size_t idx = (size_t)r * DD + j0;
                if (write_xt) {
                    // xt_next = isnan(x0) ? dinv*h : x0   (x0 already = hrn(dinv*x))
                    __half2 x0 = *(const __half2*)&g_x0[idx];
                    float2 x0f = __half22float2(x0);
                    float t0 = isnan(x0f.x) ? dv * v.x : x0f.x;
                    float t1 = isnan(x0f.y) ? dv * v.y : x0f.y;
                    *(__half2*)&g_xt[idx] = __floats2half2_rn(t0, t1);
                } else {
                    // layer 3: h stored fp16 for the final GEMM
                    *(__half2*)&g_h[idx] = __floats2half2_rn(v.x, v.y);
                }
            }
        }
    }
}

// ---------------- launch ----------------------------------------------------
extern "C" void kernel_launch(void* const* d_in, const int* in_sizes, int n_in,
                              void* d_out, int out_size) {
    const int* ei = (const int*)d_in[0];   // [2,E], int32 or int64 (detected)
    const float* x = (const float*)d_in[2];
    const void*  M = d_in[3];              // bool or int32 (detected)
    const float* W1 = (const float*)d_in[4];
    const float* b1 = (const float*)d_in[5];
    const float* c1 = (const float*)d_in[6];
    const float* W2 = (const float*)d_in[7];
    const float* b2 = (const float*)d_in[8];
    const float* c2 = (const float*)d_in[9];
    const float* W3 = (const float*)d_in[10];
    const float* b3 = (const float*)d_in[11];
    const float* c3 = (const float*)d_in[12];
    const float* Wf = (const float*)d_in[13];
    const float* bf = (const float*)d_in[14];
    float* out = (float*)d_out;

    const int TB = 256;
    int nb_e = (EE + TB - 1) / TB;
    int nb_xt = (NN * DD / 4 + TB - 1) / TB;
    int nb_spmm = (NN * 32 + TB - 1) / TB;   // 1 warp per node
    int nb_gemm = (NN + 63) / 64;            // 64-row tiles

    k_count<<<nb_e, TB>>>(ei, (const unsigned int*)M);
    k_scanA<<<NBLK, 1024>>>();
    k_xt_bucket<<<nb_xt, TB>>>(x, M, ei);

    k_spmm<<<nb_spmm, TB>>>();
    k_gemm<128, false><<<nb_gemm, 128>>>(W1, b1, c1, nullptr, 1);
    k_spmm<<<nb_spmm, TB>>>();
    k_gemm<128, false><<<nb_gemm, 128>>>(W2, b2, c2, nullptr, 1);
    k_spmm<<<nb_spmm, TB>>>();
    k_gemm<128, false><<<nb_gemm, 128>>>(W3, b3, c3, nullptr, 0);
    k_gemm<64, true><<<nb_gemm, 128>>>(Wf, bf, nullptr, out, 0);
}